// round 11
// baseline (speedup 1.0000x reference)
#include <cuda_runtime.h>
#include <cuda_fp16.h>
#include <cstdint>
#include <math.h>

#define M_TOK 512
#define H_DIM 2048
#define E_NUM 8
#define I_DIM 5632
#define P_NUM 1024

#if defined(__CUDA_ARCH__)
#  if defined(__CUDA_ARCH_FEAT_SM103_ALL) || defined(__CUDA_ARCH_FEAT_SM100_ALL)
#    define USE_TC 1
#  endif
#endif

#define BM 128
#define BN 128
#define BK 64                       // K elems per chunk = 64 halves = 128B rows
#define STAGE_A 16384               // A: 128 m-rows x 128B K-major SW128
#define STAGE_B 16384               // B: 128 n-rows x 128B K-major SW128
#define STAGE_BYTES (STAGE_A + STAGE_B)
#define SMEM_DYN_BYTES (2048 + 2 * STAGE_BYTES)
// kind::f16 idesc: dtype=F32(1<<4), atype=btype=F16(0), N=128 -> 16<<17, M=128 -> 8<<24
#define IDESC_TC ((1u << 4) | (16u << 17) | (8u << 24))

__device__ __align__(16) float g_gu[(size_t)P_NUM * 2 * I_DIM];
__device__ __align__(16) float g_h [(size_t)P_NUM * I_DIM];
__device__ __align__(16) float g_dn[(size_t)P_NUM * H_DIM];
__device__ int   g_cnt[E_NUM];
__device__ int   g_list[E_NUM * M_TOK];
__device__ float g_pw[P_NUM];

__device__ __forceinline__ uint32_t pack2(float x, float y) {
    __half2 h = __floats2half2_rn(x, y);
    return *reinterpret_cast<uint32_t*>(&h);
}
__device__ __forceinline__ uint32_t smem_u32(const void* p) {
    uint32_t a;
    asm("{ .reg .u64 t; cvta.to.shared.u64 t, %1; cvt.u32.u64 %0, t; }" : "=r"(a) : "l"(p));
    return a;
}
__device__ __forceinline__ uint32_t swz(uint32_t off) { return off ^ ((off >> 3) & 0x70); }

#ifdef USE_TC
__device__ __forceinline__ uint64_t make_desc_k(uint32_t addr) {
    // K-major SW128: layout=2, version=1, SBO=64, LBO=1 (validated by bf16 SS test)
    return 0x4000404000010000ULL | ((uint64_t)(addr >> 4) & 0x3FFF);
}
__device__ __forceinline__ void mma_f16_ss(uint32_t d, uint64_t ad, uint64_t bd, uint32_t acc) {
    asm volatile(
        "{\n\t.reg .pred p;\n\tsetp.ne.u32 p, %4, 0;\n\t"
        "tcgen05.mma.cta_group::1.kind::f16 [%0], %1, %2, %3, {%5,%5,%5,%5}, p;\n\t}"
        :: "r"(d), "l"(ad), "l"(bd), "r"(IDESC_TC), "r"(acc), "r"(0u) : "memory");
}
__device__ __forceinline__ void tc_commit(uint32_t mbar) {
    asm volatile("tcgen05.commit.cta_group::1.mbarrier::arrive::one.shared::cluster.b64 [%0];"
                 :: "r"(mbar) : "memory");
}
__device__ __forceinline__ void mbar_init(uint32_t a, uint32_t c) {
    asm volatile("mbarrier.init.shared.b64 [%0], %1;" :: "r"(a), "r"(c) : "memory");
}
__device__ __forceinline__ void mbar_wait(uint32_t a, uint32_t ph) {
    asm volatile(
        "{\n\t.reg .pred P1;\n\t"
        "WL_%=:\n\t"
        "mbarrier.try_wait.parity.acquire.cta.shared::cta.b64 P1, [%0], %1, 0x989680;\n\t"
        "@P1 bra.uni WD_%=;\n\t"
        "bra.uni WL_%=;\n\t"
        "WD_%=:\n\t}" :: "r"(a), "r"(ph) : "memory");
}
// pack rows k..k+3 x 4 n-cols of fp32 into K-major half pairs per n-col
__device__ __forceinline__ void pack_b4(const float* bp, int N, uint32_t* out) {
    float4 v0 = *(const float4*)(bp);
    float4 v1 = *(const float4*)(bp + N);
    float4 v2 = *(const float4*)(bp + 2 * (size_t)N);
    float4 v3 = *(const float4*)(bp + 3 * (size_t)N);
    out[0] = pack2(v0.x, v1.x); out[1] = pack2(v2.x, v3.x);
    out[2] = pack2(v0.y, v1.y); out[3] = pack2(v2.y, v3.y);
    out[4] = pack2(v0.z, v1.z); out[5] = pack2(v2.z, v3.z);
    out[6] = pack2(v0.w, v1.w); out[7] = pack2(v2.w, v3.w);
}
#endif

__global__ void reset_kernel() { if (threadIdx.x < E_NUM) g_cnt[threadIdx.x] = 0; }

__global__ void router_kernel(const float* __restrict__ x, const float* __restrict__ wg) {
    int warp = (blockIdx.x * blockDim.x + threadIdx.x) >> 5;
    int lane = threadIdx.x & 31;
    if (warp >= M_TOK) return;
    const float* xr = x + (long long)warp * H_DIM;
    float acc[E_NUM];
#pragma unroll
    for (int e = 0; e < E_NUM; e++) acc[e] = 0.f;
    for (int h = lane; h < H_DIM; h += 32) {
        float xv = xr[h];
        const float4* wr = (const float4*)(wg + (long long)h * E_NUM);
        float4 w0 = wr[0], w1 = wr[1];
        acc[0] += xv * w0.x; acc[1] += xv * w0.y; acc[2] += xv * w0.z; acc[3] += xv * w0.w;
        acc[4] += xv * w1.x; acc[5] += xv * w1.y; acc[6] += xv * w1.z; acc[7] += xv * w1.w;
    }
#pragma unroll
    for (int e = 0; e < E_NUM; e++)
#pragma unroll
        for (int o = 16; o > 0; o >>= 1) acc[e] += __shfl_xor_sync(0xffffffffu, acc[e], o);
    if (lane == 0) {
        float mx = acc[0];
#pragma unroll
        for (int e = 1; e < E_NUM; e++) mx = fmaxf(mx, acc[e]);
        float p[E_NUM];
#pragma unroll
        for (int e = 0; e < E_NUM; e++) p[e] = expf(acc[e] - mx);
        int i0 = 0;
#pragma unroll
        for (int e = 1; e < E_NUM; e++) if (p[e] > p[i0]) i0 = e;
        int i1 = (i0 == 0) ? 1 : 0;
#pragma unroll
        for (int e = 0; e < E_NUM; e++) { if (e == i0 || e == i1) continue; if (p[e] > p[i1]) i1 = e; }
        float denom = p[i0] + p[i1];
        int m = warp;
        g_pw[2 * m + 0] = p[i0] / denom;
        g_pw[2 * m + 1] = p[i1] / denom;
        int s0 = atomicAdd(&g_cnt[i0], 1); g_list[i0 * M_TOK + s0] = 2 * m + 0;
        int s1 = atomicAdd(&g_cnt[i1], 1); g_list[i1 * M_TOK + s1] = 2 * m + 1;
    }
}

// MODE 1: A=x (row=pair>>1), W=w1[e] (K=H,N=2I), C=g_gu. MODE 2: A=g_h, W=w2[e], C=g_dn.
template<int MODE, int KDIM>
__global__ void __launch_bounds__(256) gemm_kernel(
    const float* __restrict__ Aext, const float* __restrict__ Wbase, int N, int ldA, int ldC)
{
    const float* Asrc = (MODE == 1) ? Aext : (const float*)g_h;
    float* C = (MODE == 1) ? g_gu : g_dn;
    int e = blockIdx.z;
    int cnt = g_cnt[e];
    int row0 = blockIdx.x * BM;
    if (row0 >= cnt) return;
    int n0 = blockIdx.y * BN;
    const float* W = Wbase + (size_t)e * KDIM * N;
    int tid = threadIdx.x, lane = tid & 31, wid = tid >> 5;

#ifdef USE_TC
    constexpr int nK = KDIM / BK;
    extern __shared__ char dsm[];
    uint32_t sb = (smem_u32(dsm) + 1023) & ~1023u;
    const uint32_t tiles = sb + 1024;      // stage s at tiles + s*STAGE_BYTES

    if (wid == 0)
        asm volatile("tcgen05.alloc.cta_group::1.sync.aligned.shared::cta.b32 [%0], %1;"
                     :: "r"(sb), "r"(128u) : "memory");
    if (tid == 0) { mbar_init(sb + 8, 1); mbar_init(sb + 16, 1); }
    __syncthreads();
    uint32_t tmem;
    asm volatile("ld.shared.b32 %0, [%1];" : "=r"(tmem) : "r"(sb));

    // A producer: (m-row ar, k-half ah) -> 32 floats/chunk, K-major SW128
    int ar = tid >> 1, ah = tid & 1;
    int gr = row0 + ar;
    bool av = (gr < cnt);
    int srow = 0;
    if (av) { int p = g_list[e * M_TOK + gr]; srow = (MODE == 1) ? (p >> 1) : p; }
    const float* aG = Asrc + (size_t)srow * ldA + ah * 32;
    uint32_t aAddr[4];
#pragma unroll
    for (int j = 0; j < 4; j++) aAddr[j] = tiles + swz((uint32_t)(ar * 128 + ah * 64 + j * 16));

    // B producer: (kq=tid&15: 4 k-rows, nq=tid>>4: 8 n-cols); n-major gmem -> K-major smem
    int kq = tid & 15, nq = tid >> 4;
    const float* bG = W + (size_t)(kq * 4) * N + n0 + nq * 8;
    uint32_t bAddr[8];
#pragma unroll
    for (int c = 0; c < 8; c++)
        bAddr[c] = tiles + STAGE_A + swz((uint32_t)((nq * 8 + c) * 128 + kq * 8));

    uint32_t rap[2][16], rbp[2][16];
#pragma unroll
    for (int s = 0; s < 2; s++) {
        if (av) {
            const float4* p4 = (const float4*)(aG + s * BK);
#pragma unroll
            for (int j = 0; j < 8; j++) {
                float4 v = p4[j];
                rap[s][2 * j] = pack2(v.x, v.y); rap[s][2 * j + 1] = pack2(v.z, v.w);
            }
        } else {
#pragma unroll
            for (int j = 0; j < 16; j++) rap[s][j] = 0u;
        }
        const float* bp = bG + (size_t)s * BK * N;
        pack_b4(bp, N, &rbp[s][0]);
        pack_b4(bp + 4, N, &rbp[s][8]);
    }

    int ph0 = 0, ph1 = 0;
    for (int kt = 0; kt < nK; kt++) {
        int s = kt & 1;
        uint32_t soff = (uint32_t)s * STAGE_BYTES;
        if (kt >= 2) {
            if (s == 0) { mbar_wait(sb + 8, ph0);  ph0 ^= 1; }
            else        { mbar_wait(sb + 16, ph1); ph1 ^= 1; }
        }
#pragma unroll
        for (int j = 0; j < 4; j++)
            asm volatile("st.shared.v4.b32 [%0], {%1,%2,%3,%4};"
                :: "r"(aAddr[j] + soff), "r"(rap[s][4 * j]), "r"(rap[s][4 * j + 1]),
                   "r"(rap[s][4 * j + 2]), "r"(rap[s][4 * j + 3]) : "memory");
#pragma unroll
        for (int c = 0; c < 8; c++)
            asm volatile("st.shared.v2.b32 [%0], {%1,%2};"
                :: "r"(bAddr[c] + soff), "r"(rbp[s][2 * c]), "r"(rbp[s][2 * c + 1]) : "memory");
        asm volatile("fence.proxy.async.shared::cta;" ::: "memory");
        __syncthreads();

        if (tid == 0) {
            asm volatile("tcgen05.fence::after_thread_sync;" ::: "memory");
            uint64_t ad = make_desc_k(tiles + soff);
            uint64_t bd = make_desc_k(tiles + soff + STAGE_A);
#pragma unroll
            for (int ks = 0; ks < 4; ks++)   // K=16 per mma, +2 desc units (32B), as in bf16 test
                mma_f16_ss(tmem, ad + ks * 2, bd + ks * 2, (uint32_t)((kt | ks) != 0));
            tc_commit(sb + 8 + 8 * s);
        }

        if (kt + 2 < nK) {
            if (av) {
                const float4* p4 = (const float4*)(aG + (kt + 2) * BK);
#pragma unroll
                for (int j = 0; j < 8; j++) {
                    float4 v = p4[j];
                    rap[s][2 * j] = pack2(v.x, v.y); rap[s][2 * j + 1] = pack2(v.z, v.w);
                }
            }
            const float* bp = bG + (size_t)(kt + 2) * BK * N;
            pack_b4(bp, N, &rbp[s][0]);
            pack_b4(bp + 4, N, &rbp[s][8]);
        }
    }

    if (((nK - 1) & 1) == 0) mbar_wait(sb + 8, ph0);
    else                     mbar_wait(sb + 16, ph1);
    asm volatile("tcgen05.fence::after_thread_sync;" ::: "memory");

    if (wid < 4) {
        int m = wid * 32 + lane;
        int grm = row0 + m;
        float* dst = (float*)0;
        if (grm < cnt) { int p = g_list[e * M_TOK + grm]; dst = C + (size_t)p * ldC + n0; }
#pragma unroll
        for (int cb = 0; cb < BN; cb += 32) {
            uint32_t r[32];
            asm volatile(
                "tcgen05.ld.sync.aligned.32x32b.x32.b32 "
                "{%0,%1,%2,%3,%4,%5,%6,%7,%8,%9,%10,%11,%12,%13,%14,%15,"
                "%16,%17,%18,%19,%20,%21,%22,%23,%24,%25,%26,%27,%28,%29,%30,%31}, [%32];"
                : "=r"(r[0]), "=r"(r[1]), "=r"(r[2]), "=r"(r[3]), "=r"(r[4]), "=r"(r[5]),
                  "=r"(r[6]), "=r"(r[7]), "=r"(r[8]), "=r"(r[9]), "=r"(r[10]), "=r"(r[11]),
                  "=r"(r[12]), "=r"(r[13]), "=r"(r[14]), "=r"(r[15]), "=r"(r[16]), "=r"(r[17]),
                  "=r"(r[18]), "=r"(r[19]), "=r"(r[20]), "=r"(r[21]), "=r"(r[22]), "=r"(r[23]),
                  "=r"(r[24]), "=r"(r[25]), "=r"(r[26]), "=r"(r[27]), "=r"(r[28]), "=r"(r[29]),
                  "=r"(r[30]), "=r"(r[31])
                : "r"(tmem + cb));
            asm volatile("tcgen05.wait::ld.sync.aligned;" ::: "memory");
            if (dst) {
#pragma unroll
                for (int j = 0; j < 8; j++) {
                    float4 v;
                    v.x = __uint_as_float(r[4 * j + 0]); v.y = __uint_as_float(r[4 * j + 1]);
                    v.z = __uint_as_float(r[4 * j + 2]); v.w = __uint_as_float(r[4 * j + 3]);
                    *(float4*)(dst + cb + 4 * j) = v;
                }
            }
        }
    }
    __syncthreads();
    if (wid == 0) {
        asm volatile("tcgen05.relinquish_alloc_permit.cta_group::1.sync.aligned;");
        asm volatile("tcgen05.dealloc.cta_group::1.sync.aligned.b32 %0, %1;" :: "r"(tmem), "r"(128u));
    }
#else
    // Never-selected safety net (a-cubin is picked at runtime): naive correct GEMM.
    for (int r = tid >> 5; row0 + r < cnt && r < BM; r += 8) {
        int p = g_list[e * M_TOK + row0 + r];
        int sr = (MODE == 1) ? (p >> 1) : p;
        const float* a = Asrc + (size_t)sr * ldA;
        for (int n = lane; n < BN; n += 32) {
            float acc = 0.f;
            for (int k = 0; k < KDIM; k++) acc += a[k] * W[(size_t)k * N + n0 + n];
            C[(size_t)p * ldC + n0 + n] = acc;
        }
    }
#endif
}

__global__ void silu_mul_kernel() {
    const int I4 = I_DIM / 4;
    long long idx = (long long)blockIdx.x * blockDim.x + threadIdx.x;
    long long p = idx / I4;
    int i4 = (int)(idx % I4);
    const float* gp = g_gu + p * (2 * I_DIM);
    float4 gv = *(const float4*)(gp + i4 * 4);
    float4 uv = *(const float4*)(gp + I_DIM + i4 * 4);
    float4 h;
    h.x = gv.x / (1.f + expf(-gv.x)) * uv.x;
    h.y = gv.y / (1.f + expf(-gv.y)) * uv.y;
    h.z = gv.z / (1.f + expf(-gv.z)) * uv.z;
    h.w = gv.w / (1.f + expf(-gv.w)) * uv.w;
    *(float4*)(g_h + p * I_DIM + i4 * 4) = h;
}

__global__ void combine_kernel(float* __restrict__ out) {
    const int H4 = H_DIM / 4;
    int idx = blockIdx.x * blockDim.x + threadIdx.x;
    int m = idx / H4;
    int h4 = idx % H4;
    float w0 = g_pw[2 * m + 0];
    float w1 = g_pw[2 * m + 1];
    float4 d0 = *(const float4*)(g_dn + (long long)(2 * m + 0) * H_DIM + h4 * 4);
    float4 d1 = *(const float4*)(g_dn + (long long)(2 * m + 1) * H_DIM + h4 * 4);
    float4 o;
    o.x = w0 * d0.x + w1 * d1.x;
    o.y = w0 * d0.y + w1 * d1.y;
    o.z = w0 * d0.z + w1 * d1.z;
    o.w = w0 * d0.w + w1 * d1.w;
    *(float4*)(out + (long long)m * H_DIM + h4 * 4) = o;
}

extern "C" void kernel_launch(void* const* d_in, const int* in_sizes, int n_in,
                              void* d_out, int out_size) {
    const float* x  = (const float*)d_in[0];
    const float* wg = (const float*)d_in[1];
    const float* w1 = (const float*)d_in[2];
    const float* w2 = (const float*)d_in[3];
    float* out = (float*)d_out;
    (void)in_sizes; (void)n_in; (void)out_size;

    cudaFuncSetAttribute(gemm_kernel<1, H_DIM>,
                         cudaFuncAttributeMaxDynamicSharedMemorySize, SMEM_DYN_BYTES);
    cudaFuncSetAttribute(gemm_kernel<2, I_DIM>,
                         cudaFuncAttributeMaxDynamicSharedMemorySize, SMEM_DYN_BYTES);

    reset_kernel<<<1, 32>>>();
    router_kernel<<<M_TOK / 8, 256>>>(x, wg);

    dim3 grid1(M_TOK / BM, (2 * I_DIM) / BN, E_NUM);
    gemm_kernel<1, H_DIM><<<grid1, 256, SMEM_DYN_BYTES>>>(x, w1, 2 * I_DIM, H_DIM, 2 * I_DIM);

    silu_mul_kernel<<<(P_NUM * (I_DIM / 4)) / 256, 256>>>();

    dim3 grid2(M_TOK / BM, H_DIM / BN, E_NUM);
    gemm_kernel<2, I_DIM><<<grid2, 256, SMEM_DYN_BYTES>>>(x, w2, H_DIM, I_DIM, H_DIM);

    combine_kernel<<<(M_TOK * (H_DIM / 4)) / 256, 256>>>(out);
}

// round 12
// speedup vs baseline: 1.2121x; 1.2121x over previous
#include <cuda_runtime.h>
#include <cuda_fp16.h>
#include <cstdint>
#include <math.h>

#define M_TOK 512
#define H_DIM 2048
#define E_NUM 8
#define I_DIM 5632
#define P_NUM 1024

#if defined(__CUDA_ARCH__)
#  if defined(__CUDA_ARCH_FEAT_SM103_ALL) || defined(__CUDA_ARCH_FEAT_SM100_ALL)
#    define USE_TC 1
#  endif
#endif

#define BM 128
#define BN 128
#define BK 64                       // K elems per chunk = 64 halves = 128B rows
#define STAGE_A 16384               // A: 128 m-rows x 128B K-major SW128
#define STAGE_B 16384               // B: 128 n-rows x 128B K-major SW128
#define STAGE_BYTES (STAGE_A + STAGE_B)
#define SMEM_DYN_BYTES (2048 + 2 * STAGE_BYTES)
// kind::f16 idesc: dtype=F32(1<<4), atype=btype=F16(0), N=128 -> 16<<17, M=128 -> 8<<24
#define IDESC_TC ((1u << 4) | (16u << 17) | (8u << 24))

__device__ __align__(16) float g_gu[(size_t)P_NUM * 2 * I_DIM];
__device__ __align__(16) float g_h [(size_t)P_NUM * I_DIM];
__device__ __align__(16) float g_dn[(size_t)P_NUM * H_DIM];
__device__ int   g_cnt[E_NUM];
__device__ int   g_list[E_NUM * M_TOK];
__device__ float g_pw[P_NUM];

__device__ __forceinline__ uint32_t pack2(float x, float y) {
    __half2 h = __floats2half2_rn(x, y);
    return *reinterpret_cast<uint32_t*>(&h);
}
__device__ __forceinline__ uint32_t smem_u32(const void* p) {
    uint32_t a;
    asm("{ .reg .u64 t; cvta.to.shared.u64 t, %1; cvt.u32.u64 %0, t; }" : "=r"(a) : "l"(p));
    return a;
}
__device__ __forceinline__ uint32_t swz(uint32_t off) { return off ^ ((off >> 3) & 0x70); }

#ifdef USE_TC
__device__ __forceinline__ uint64_t make_desc_k(uint32_t addr) {
    // K-major SW128: layout=2, version=1, SBO=64, LBO=1 (validated)
    return 0x4000404000010000ULL | ((uint64_t)(addr >> 4) & 0x3FFF);
}
__device__ __forceinline__ void mma_f16_ss(uint32_t d, uint64_t ad, uint64_t bd, uint32_t acc) {
    asm volatile(
        "{\n\t.reg .pred p;\n\tsetp.ne.u32 p, %4, 0;\n\t"
        "tcgen05.mma.cta_group::1.kind::f16 [%0], %1, %2, %3, {%5,%5,%5,%5}, p;\n\t}"
        :: "r"(d), "l"(ad), "l"(bd), "r"(IDESC_TC), "r"(acc), "r"(0u) : "memory");
}
__device__ __forceinline__ void tc_commit(uint32_t mbar) {
    asm volatile("tcgen05.commit.cta_group::1.mbarrier::arrive::one.shared::cluster.b64 [%0];"
                 :: "r"(mbar) : "memory");
}
__device__ __forceinline__ void mbar_init(uint32_t a, uint32_t c) {
    asm volatile("mbarrier.init.shared.b64 [%0], %1;" :: "r"(a), "r"(c) : "memory");
}
__device__ __forceinline__ void mbar_wait(uint32_t a, uint32_t ph) {
    asm volatile(
        "{\n\t.reg .pred P1;\n\t"
        "WL_%=:\n\t"
        "mbarrier.try_wait.parity.acquire.cta.shared::cta.b64 P1, [%0], %1, 0x989680;\n\t"
        "@P1 bra.uni WD_%=;\n\t"
        "bra.uni WL_%=;\n\t"
        "WD_%=:\n\t}" :: "r"(a), "r"(ph) : "memory");
}

// Batched prefetch: issue ALL 16 LDG.128 (MLP=16) before any cvt/pack.
// rap is written only when av (otherwise it keeps its prologue zeros).
__device__ __forceinline__ void ld_pack(const float* aG, bool av, const float* bG, int N,
                                        int koff, uint32_t* rap, uint32_t* rbp) {
    // ---- B raw loads: rows k..k+3 at n-offsets 0 and +4 ----
    float4 tb[8];
    const float* bp = bG + (size_t)koff * N;
#pragma unroll
    for (int r = 0; r < 4; r++) tb[r]     = *(const float4*)(bp + (size_t)r * N);
#pragma unroll
    for (int r = 0; r < 4; r++) tb[4 + r] = *(const float4*)(bp + (size_t)r * N + 4);
    // ---- A raw loads (issued before any pack) ----
    if (av) {
        float4 ta[8];
        const float4* ap = (const float4*)(aG + koff);
#pragma unroll
        for (int j = 0; j < 8; j++) ta[j] = ap[j];
#pragma unroll
        for (int j = 0; j < 8; j++) {
            rap[2 * j]     = pack2(ta[j].x, ta[j].y);
            rap[2 * j + 1] = pack2(ta[j].z, ta[j].w);
        }
    }
    // ---- B pack: K-major half pairs per n-col (identical mapping to R11 pack_b4) ----
#pragma unroll
    for (int h = 0; h < 2; h++) {
        rbp[8 * h + 0] = pack2(tb[4 * h + 0].x, tb[4 * h + 1].x);
        rbp[8 * h + 1] = pack2(tb[4 * h + 2].x, tb[4 * h + 3].x);
        rbp[8 * h + 2] = pack2(tb[4 * h + 0].y, tb[4 * h + 1].y);
        rbp[8 * h + 3] = pack2(tb[4 * h + 2].y, tb[4 * h + 3].y);
        rbp[8 * h + 4] = pack2(tb[4 * h + 0].z, tb[4 * h + 1].z);
        rbp[8 * h + 5] = pack2(tb[4 * h + 2].z, tb[4 * h + 3].z);
        rbp[8 * h + 6] = pack2(tb[4 * h + 0].w, tb[4 * h + 1].w);
        rbp[8 * h + 7] = pack2(tb[4 * h + 2].w, tb[4 * h + 3].w);
    }
}
#endif

__global__ void reset_kernel() { if (threadIdx.x < E_NUM) g_cnt[threadIdx.x] = 0; }

__global__ void router_kernel(const float* __restrict__ x, const float* __restrict__ wg) {
    int warp = (blockIdx.x * blockDim.x + threadIdx.x) >> 5;
    int lane = threadIdx.x & 31;
    if (warp >= M_TOK) return;
    const float* xr = x + (long long)warp * H_DIM;
    float acc[E_NUM];
#pragma unroll
    for (int e = 0; e < E_NUM; e++) acc[e] = 0.f;
    for (int h = lane; h < H_DIM; h += 32) {
        float xv = xr[h];
        const float4* wr = (const float4*)(wg + (long long)h * E_NUM);
        float4 w0 = wr[0], w1 = wr[1];
        acc[0] += xv * w0.x; acc[1] += xv * w0.y; acc[2] += xv * w0.z; acc[3] += xv * w0.w;
        acc[4] += xv * w1.x; acc[5] += xv * w1.y; acc[6] += xv * w1.z; acc[7] += xv * w1.w;
    }
#pragma unroll
    for (int e = 0; e < E_NUM; e++)
#pragma unroll
        for (int o = 16; o > 0; o >>= 1) acc[e] += __shfl_xor_sync(0xffffffffu, acc[e], o);
    if (lane == 0) {
        float mx = acc[0];
#pragma unroll
        for (int e = 1; e < E_NUM; e++) mx = fmaxf(mx, acc[e]);
        float p[E_NUM];
#pragma unroll
        for (int e = 0; e < E_NUM; e++) p[e] = expf(acc[e] - mx);
        int i0 = 0;
#pragma unroll
        for (int e = 1; e < E_NUM; e++) if (p[e] > p[i0]) i0 = e;
        int i1 = (i0 == 0) ? 1 : 0;
#pragma unroll
        for (int e = 0; e < E_NUM; e++) { if (e == i0 || e == i1) continue; if (p[e] > p[i1]) i1 = e; }
        float denom = p[i0] + p[i1];
        int m = warp;
        g_pw[2 * m + 0] = p[i0] / denom;
        g_pw[2 * m + 1] = p[i1] / denom;
        int s0 = atomicAdd(&g_cnt[i0], 1); g_list[i0 * M_TOK + s0] = 2 * m + 0;
        int s1 = atomicAdd(&g_cnt[i1], 1); g_list[i1 * M_TOK + s1] = 2 * m + 1;
    }
}

// MODE 1: A=x (row=pair>>1), W=w1[e] (K=H,N=2I), C=g_gu. MODE 2: A=g_h, W=w2[e], C=g_dn.
template<int MODE, int KDIM>
__global__ void __launch_bounds__(256) gemm_kernel(
    const float* __restrict__ Aext, const float* __restrict__ Wbase, int N, int ldA, int ldC)
{
    const float* Asrc = (MODE == 1) ? Aext : (const float*)g_h;
    float* C = (MODE == 1) ? g_gu : g_dn;
    int e = blockIdx.z;
    int cnt = g_cnt[e];
    int row0 = blockIdx.x * BM;
    if (row0 >= cnt) return;
    int n0 = blockIdx.y * BN;
    const float* W = Wbase + (size_t)e * KDIM * N;
    int tid = threadIdx.x, lane = tid & 31, wid = tid >> 5;

#ifdef USE_TC
    constexpr int nK = KDIM / BK;
    extern __shared__ char dsm[];
    uint32_t sb = (smem_u32(dsm) + 1023) & ~1023u;
    const uint32_t tiles = sb + 1024;      // stage s at tiles + s*STAGE_BYTES

    if (wid == 0)
        asm volatile("tcgen05.alloc.cta_group::1.sync.aligned.shared::cta.b32 [%0], %1;"
                     :: "r"(sb), "r"(128u) : "memory");
    if (tid == 0) { mbar_init(sb + 8, 1); mbar_init(sb + 16, 1); }
    __syncthreads();
    uint32_t tmem;
    asm volatile("ld.shared.b32 %0, [%1];" : "=r"(tmem) : "r"(sb));

    // A producer: (m-row ar, k-half ah) -> 32 floats/chunk, K-major SW128
    int ar = tid >> 1, ah = tid & 1;
    int gr = row0 + ar;
    bool av = (gr < cnt);
    int srow = 0;
    if (av) { int p = g_list[e * M_TOK + gr]; srow = (MODE == 1) ? (p >> 1) : p; }
    const float* aG = Asrc + (size_t)srow * ldA + ah * 32;
    uint32_t aAddr[4];
#pragma unroll
    for (int j = 0; j < 4; j++) aAddr[j] = tiles + swz((uint32_t)(ar * 128 + ah * 64 + j * 16));

    // B producer: (kq=tid&15: 4 k-rows, nq=tid>>4: 8 n-cols); n-major gmem -> K-major smem
    int kq = tid & 15, nq = tid >> 4;
    const float* bG = W + (size_t)(kq * 4) * N + n0 + nq * 8;
    uint32_t bAddr[8];
#pragma unroll
    for (int c = 0; c < 8; c++)
        bAddr[c] = tiles + STAGE_A + swz((uint32_t)((nq * 8 + c) * 128 + kq * 8));

    uint32_t rap[2][16], rbp[2][16];
#pragma unroll
    for (int s = 0; s < 2; s++)
#pragma unroll
        for (int j = 0; j < 16; j++) rap[s][j] = 0u;
    ld_pack(aG, av, bG, N, 0,  rap[0], rbp[0]);
    ld_pack(aG, av, bG, N, BK, rap[1], rbp[1]);

    int ph0 = 0, ph1 = 0;
    for (int kt = 0; kt < nK; kt++) {
        int s = kt & 1;
        uint32_t soff = (uint32_t)s * STAGE_BYTES;
        if (kt >= 2) {
            if (s == 0) { mbar_wait(sb + 8, ph0);  ph0 ^= 1; }
            else        { mbar_wait(sb + 16, ph1); ph1 ^= 1; }
        }
#pragma unroll
        for (int j = 0; j < 4; j++)
            asm volatile("st.shared.v4.b32 [%0], {%1,%2,%3,%4};"
                :: "r"(aAddr[j] + soff), "r"(rap[s][4 * j]), "r"(rap[s][4 * j + 1]),
                   "r"(rap[s][4 * j + 2]), "r"(rap[s][4 * j + 3]) : "memory");
#pragma unroll
        for (int c = 0; c < 8; c++)
            asm volatile("st.shared.v2.b32 [%0], {%1,%2};"
                :: "r"(bAddr[c] + soff), "r"(rbp[s][2 * c]), "r"(rbp[s][2 * c + 1]) : "memory");
        asm volatile("fence.proxy.async.shared::cta;" ::: "memory");
        __syncthreads();

        if (tid == 0) {
            asm volatile("tcgen05.fence::after_thread_sync;" ::: "memory");
            uint64_t ad = make_desc_k(tiles + soff);
            uint64_t bd = make_desc_k(tiles + soff + STAGE_A);
#pragma unroll
            for (int ks = 0; ks < 4; ks++)   // K=16 per mma, +2 desc units (32B)
                mma_f16_ss(tmem, ad + ks * 2, bd + ks * 2, (uint32_t)((kt | ks) != 0));
            tc_commit(sb + 8 + 8 * s);
        }

        if (kt + 2 < nK)
            ld_pack(aG, av, bG, N, (kt + 2) * BK, rap[s], rbp[s]);
    }

    if (((nK - 1) & 1) == 0) mbar_wait(sb + 8, ph0);
    else                     mbar_wait(sb + 16, ph1);
    asm volatile("tcgen05.fence::after_thread_sync;" ::: "memory");

    if (wid < 4) {
        int m = wid * 32 + lane;
        int grm = row0 + m;
        float* dst = (float*)0;
        if (grm < cnt) { int p = g_list[e * M_TOK + grm]; dst = C + (size_t)p * ldC + n0; }
#pragma unroll
        for (int cb = 0; cb < BN; cb += 32) {
            uint32_t r[32];
            asm volatile(
                "tcgen05.ld.sync.aligned.32x32b.x32.b32 "
                "{%0,%1,%2,%3,%4,%5,%6,%7,%8,%9,%10,%11,%12,%13,%14,%15,"
                "%16,%17,%18,%19,%20,%21,%22,%23,%24,%25,%26,%27,%28,%29,%30,%31}, [%32];"
                : "=r"(r[0]), "=r"(r[1]), "=r"(r[2]), "=r"(r[3]), "=r"(r[4]), "=r"(r[5]),
                  "=r"(r[6]), "=r"(r[7]), "=r"(r[8]), "=r"(r[9]), "=r"(r[10]), "=r"(r[11]),
                  "=r"(r[12]), "=r"(r[13]), "=r"(r[14]), "=r"(r[15]), "=r"(r[16]), "=r"(r[17]),
                  "=r"(r[18]), "=r"(r[19]), "=r"(r[20]), "=r"(r[21]), "=r"(r[22]), "=r"(r[23]),
                  "=r"(r[24]), "=r"(r[25]), "=r"(r[26]), "=r"(r[27]), "=r"(r[28]), "=r"(r[29]),
                  "=r"(r[30]), "=r"(r[31])
                : "r"(tmem + cb));
            asm volatile("tcgen05.wait::ld.sync.aligned;" ::: "memory");
            if (dst) {
#pragma unroll
                for (int j = 0; j < 8; j++) {
                    float4 v;
                    v.x = __uint_as_float(r[4 * j + 0]); v.y = __uint_as_float(r[4 * j + 1]);
                    v.z = __uint_as_float(r[4 * j + 2]); v.w = __uint_as_float(r[4 * j + 3]);
                    *(float4*)(dst + cb + 4 * j) = v;
                }
            }
        }
    }
    __syncthreads();
    if (wid == 0) {
        asm volatile("tcgen05.relinquish_alloc_permit.cta_group::1.sync.aligned;");
        asm volatile("tcgen05.dealloc.cta_group::1.sync.aligned.b32 %0, %1;" :: "r"(tmem), "r"(128u));
    }
#else
    // Never-selected safety net (a-cubin is picked at runtime): naive correct GEMM.
    for (int r = tid >> 5; row0 + r < cnt && r < BM; r += 8) {
        int p = g_list[e * M_TOK + row0 + r];
        int sr = (MODE == 1) ? (p >> 1) : p;
        const float* a = Asrc + (size_t)sr * ldA;
        for (int n = lane; n < BN; n += 32) {
            float acc = 0.f;
            for (int k = 0; k < KDIM; k++) acc += a[k] * W[(size_t)k * N + n0 + n];
            C[(size_t)p * ldC + n0 + n] = acc;
        }
    }
#endif
}

__global__ void silu_mul_kernel() {
    const int I4 = I_DIM / 4;
    long long idx = (long long)blockIdx.x * blockDim.x + threadIdx.x;
    long long p = idx / I4;
    int i4 = (int)(idx % I4);
    const float* gp = g_gu + p * (2 * I_DIM);
    float4 gv = *(const float4*)(gp + i4 * 4);
    float4 uv = *(const float4*)(gp + I_DIM + i4 * 4);
    float4 h;
    h.x = gv.x / (1.f + expf(-gv.x)) * uv.x;
    h.y = gv.y / (1.f + expf(-gv.y)) * uv.y;
    h.z = gv.z / (1.f + expf(-gv.z)) * uv.z;
    h.w = gv.w / (1.f + expf(-gv.w)) * uv.w;
    *(float4*)(g_h + p * I_DIM + i4 * 4) = h;
}

__global__ void combine_kernel(float* __restrict__ out) {
    const int H4 = H_DIM / 4;
    int idx = blockIdx.x * blockDim.x + threadIdx.x;
    int m = idx / H4;
    int h4 = idx % H4;
    float w0 = g_pw[2 * m + 0];
    float w1 = g_pw[2 * m + 1];
    float4 d0 = *(const float4*)(g_dn + (long long)(2 * m + 0) * H_DIM + h4 * 4);
    float4 d1 = *(const float4*)(g_dn + (long long)(2 * m + 1) * H_DIM + h4 * 4);
    float4 o;
    o.x = w0 * d0.x + w1 * d1.x;
    o.y = w0 * d0.y + w1 * d1.y;
    o.z = w0 * d0.z + w1 * d1.z;
    o.w = w0 * d0.w + w1 * d1.w;
    *(float4*)(out + (long long)m * H_DIM + h4 * 4) = o;
}

extern "C" void kernel_launch(void* const* d_in, const int* in_sizes, int n_in,
                              void* d_out, int out_size) {
    const float* x  = (const float*)d_in[0];
    const float* wg = (const float*)d_in[1];
    const float* w1 = (const float*)d_in[2];
    const float* w2 = (const float*)d_in[3];
    float* out = (float*)d_out;
    (void)in_sizes; (void)n_in; (void)out_size;

    cudaFuncSetAttribute(gemm_kernel<1, H_DIM>,
                         cudaFuncAttributeMaxDynamicSharedMemorySize, SMEM_DYN_BYTES);
    cudaFuncSetAttribute(gemm_kernel<2, I_DIM>,
                         cudaFuncAttributeMaxDynamicSharedMemorySize, SMEM_DYN_BYTES);

    reset_kernel<<<1, 32>>>();
    router_kernel<<<M_TOK / 8, 256>>>(x, wg);

    dim3 grid1(M_TOK / BM, (2 * I_DIM) / BN, E_NUM);
    gemm_kernel<1, H_DIM><<<grid1, 256, SMEM_DYN_BYTES>>>(x, w1, 2 * I_DIM, H_DIM, 2 * I_DIM);

    silu_mul_kernel<<<(P_NUM * (I_DIM / 4)) / 256, 256>>>();

    dim3 grid2(M_TOK / BM, H_DIM / BN, E_NUM);
    gemm_kernel<2, I_DIM><<<grid2, 256, SMEM_DYN_BYTES>>>(x, w2, H_DIM, I_DIM, H_DIM);

    combine_kernel<<<(M_TOK * (H_DIM / 4)) / 256, 256>>>(out);
}

// round 14
// speedup vs baseline: 2.5137x; 2.0739x over previous
#include <cuda_runtime.h>
#include <cuda_fp16.h>
#include <cstdint>
#include <math.h>

#define M_TOK 512
#define H_DIM 2048
#define E_NUM 8
#define I_DIM 5632
#define P_NUM 1024

#if defined(__CUDA_ARCH__)
#  if defined(__CUDA_ARCH_FEAT_SM103_ALL) || defined(__CUDA_ARCH_FEAT_SM100_ALL)
#    define USE_TC 1
#  endif
#endif

#define BM 128
#define BN 128
#define BK 64                       // K elems per chunk = 64 halves = 128B rows
#define STAGE_A 16384               // A: 128 m-rows x 128B K-major SW128
#define STAGE_B 16384               // B: 128 n-rows x 128B K-major SW128
#define STAGE_BYTES (STAGE_A + STAGE_B)
#define SMEM_DYN_BYTES (2048 + 2 * STAGE_BYTES)
// kind::f16 idesc: dtype=F32(1<<4), atype=btype=F16(0), N=128 -> 16<<17, M=128 -> 8<<24
// (validated correct in R11/R12: rel_err 5.13e-4)
#define IDESC_TC ((1u << 4) | (16u << 17) | (8u << 24))

__device__ __align__(16) float g_gu[(size_t)P_NUM * 2 * I_DIM];
__device__ __align__(16) float g_h [(size_t)P_NUM * I_DIM];
__device__ __align__(16) float g_dn[(size_t)P_NUM * H_DIM];
__device__ int   g_cnt[E_NUM];
__device__ int   g_list[E_NUM * M_TOK];
__device__ float g_pw[P_NUM];

__device__ __forceinline__ uint32_t pack2(float x, float y) {
    __half2 h = __floats2half2_rn(x, y);
    return *reinterpret_cast<uint32_t*>(&h);
}
__device__ __forceinline__ uint32_t smem_u32(const void* p) {
    uint32_t a;
    asm("{ .reg .u64 t; cvta.to.shared.u64 t, %1; cvt.u32.u64 %0, t; }" : "=r"(a) : "l"(p));
    return a;
}
__device__ __forceinline__ uint32_t swz(uint32_t off) { return off ^ ((off >> 3) & 0x70); }

#ifdef USE_TC
__device__ __forceinline__ uint64_t make_desc_k(uint32_t addr) {
    // K-major SW128: layout=2, version=1, SBO=64, LBO=1 (validated)
    return 0x4000404000010000ULL | ((uint64_t)(addr >> 4) & 0x3FFF);
}
__device__ __forceinline__ void mma_f16_ss(uint32_t d, uint64_t ad, uint64_t bd, uint32_t acc) {
    asm volatile(
        "{\n\t.reg .pred p;\n\tsetp.ne.u32 p, %4, 0;\n\t"
        "tcgen05.mma.cta_group::1.kind::f16 [%0], %1, %2, %3, {%5,%5,%5,%5}, p;\n\t}"
        :: "r"(d), "l"(ad), "l"(bd), "r"(IDESC_TC), "r"(acc), "r"(0u) : "memory");
}
__device__ __forceinline__ void tc_commit(uint32_t mbar) {
    asm volatile("tcgen05.commit.cta_group::1.mbarrier::arrive::one.shared::cluster.b64 [%0];"
                 :: "r"(mbar) : "memory");
}
__device__ __forceinline__ void mbar_init(uint32_t a, uint32_t c) {
    asm volatile("mbarrier.init.shared.b64 [%0], %1;" :: "r"(a), "r"(c) : "memory");
}
__device__ __forceinline__ void mbar_wait(uint32_t a, uint32_t ph) {
    asm volatile(
        "{\n\t.reg .pred P1;\n\t"
        "WL_%=:\n\t"
        "mbarrier.try_wait.parity.acquire.cta.shared::cta.b64 P1, [%0], %1, 0x989680;\n\t"
        "@P1 bra.uni WD_%=;\n\t"
        "bra.uni WL_%=;\n\t"
        "WD_%=:\n\t}" :: "r"(a), "r"(ph) : "memory");
}
#endif

__global__ void reset_kernel() { if (threadIdx.x < E_NUM) g_cnt[threadIdx.x] = 0; }

__global__ void router_kernel(const float* __restrict__ x, const float* __restrict__ wg) {
    int warp = (blockIdx.x * blockDim.x + threadIdx.x) >> 5;
    int lane = threadIdx.x & 31;
    if (warp >= M_TOK) return;
    const float* xr = x + (long long)warp * H_DIM;
    float acc[E_NUM];
#pragma unroll
    for (int e = 0; e < E_NUM; e++) acc[e] = 0.f;
    for (int h = lane; h < H_DIM; h += 32) {
        float xv = xr[h];
        const float4* wr = (const float4*)(wg + (long long)h * E_NUM);
        float4 w0 = wr[0], w1 = wr[1];
        acc[0] += xv * w0.x; acc[1] += xv * w0.y; acc[2] += xv * w0.z; acc[3] += xv * w0.w;
        acc[4] += xv * w1.x; acc[5] += xv * w1.y; acc[6] += xv * w1.z; acc[7] += xv * w1.w;
    }
#pragma unroll
    for (int e = 0; e < E_NUM; e++)
#pragma unroll
        for (int o = 16; o > 0; o >>= 1) acc[e] += __shfl_xor_sync(0xffffffffu, acc[e], o);
    if (lane == 0) {
        float mx = acc[0];
#pragma unroll
        for (int e = 1; e < E_NUM; e++) mx = fmaxf(mx, acc[e]);
        float p[E_NUM];
#pragma unroll
        for (int e = 0; e < E_NUM; e++) p[e] = expf(acc[e] - mx);
        int i0 = 0;
#pragma unroll
        for (int e = 1; e < E_NUM; e++) if (p[e] > p[i0]) i0 = e;
        int i1 = (i0 == 0) ? 1 : 0;
#pragma unroll
        for (int e = 0; e < E_NUM; e++) { if (e == i0 || e == i1) continue; if (p[e] > p[i1]) i1 = e; }
        float denom = p[i0] + p[i1];
        int m = warp;
        g_pw[2 * m + 0] = p[i0] / denom;
        g_pw[2 * m + 1] = p[i1] / denom;
        int s0 = atomicAdd(&g_cnt[i0], 1); g_list[i0 * M_TOK + s0] = 2 * m + 0;
        int s1 = atomicAdd(&g_cnt[i1], 1); g_list[i1 * M_TOK + s1] = 2 * m + 1;
    }
}

// MODE 1: A=x (row=pair>>1), W=w1[e] (K=H,N=2I), C=g_gu. MODE 2: A=g_h, W=w2[e], C=g_dn.
template<int MODE, int KDIM>
__global__ void __launch_bounds__(256) gemm_kernel(
    const float* __restrict__ Aext, const float* __restrict__ Wbase, int N, int ldA, int ldC)
{
    const float* Asrc = (MODE == 1) ? Aext : (const float*)g_h;
    float* C = (MODE == 1) ? g_gu : g_dn;
    int e = blockIdx.z;
    int cnt = g_cnt[e];
    int row0 = blockIdx.x * BM;
    if (row0 >= cnt) return;
    int n0 = blockIdx.y * BN;
    const float* W = Wbase + (size_t)e * KDIM * N;
    int tid = threadIdx.x, lane = tid & 31, wid = tid >> 5;

#ifdef USE_TC
    constexpr int nK = KDIM / BK;
    extern __shared__ char dsm[];
    uint32_t sb = (smem_u32(dsm) + 1023) & ~1023u;
    const uint32_t tiles = sb + 1024;      // stage s at tiles + s*STAGE_BYTES

    if (wid == 0)
        asm volatile("tcgen05.alloc.cta_group::1.sync.aligned.shared::cta.b32 [%0], %1;"
                     :: "r"(sb), "r"(128u) : "memory");
    if (tid == 0) { mbar_init(sb + 8, 1); mbar_init(sb + 16, 1); }
    __syncthreads();
    uint32_t tmem;
    asm volatile("ld.shared.b32 %0, [%1];" : "=r"(tmem) : "r"(sb));

    // ---- A producer (unchanged from R13): warp w owns m-rows w*16..+15;
    // lane=(l2=lane>>4, seg=lane&15). LDG: 2 rows x 256B (4 lines). STS: 2 full rows (2 phases).
    int l2 = lane >> 4, seg = lane & 15;
    const float* aP[8];
    uint32_t aAddr[8];
    bool av[8];
#pragma unroll
    for (int j = 0; j < 8; j++) {
        int rl = wid * 16 + l2 + 2 * j;
        int grm = row0 + rl;
        av[j] = (grm < cnt);
        int srow = 0;
        if (av[j]) { int p = g_list[e * M_TOK + grm]; srow = (MODE == 1) ? (p >> 1) : p; }
        aP[j] = Asrc + (size_t)srow * ldA + seg * 4;
        aAddr[j] = tiles + swz((uint32_t)(rl * 128 + seg * 8));
    }

    // ---- B producer (K-major smem, NEW mapping: coalesced LDG + conflict-free STS) ----
    // thread -> k-group kg=(l>>3)|4(w&1) (8 consecutive k), n-quad nq=(w>>1)*8+(l&7).
    // LDG instr: 4 k-rows x 128B contiguous (4 full lines).
    // STS: per n-col c one v4 (16B) at row 4nq+c, col kg; swizzled cols span all 8 -> 4 phases.
    int kg = (lane >> 3) | ((wid & 1) << 2);
    int nq = ((wid >> 1) << 3) | (lane & 7);
    const float* bP = W + (size_t)(kg * 8) * N + n0 + nq * 4;
    uint32_t bAddr[4];
#pragma unroll
    for (int c = 0; c < 4; c++)
        bAddr[c] = tiles + STAGE_A + swz((uint32_t)((nq * 4 + c) * 128 + kg * 16));

    int ph0 = 0, ph1 = 0;
    for (int kt = 0; kt < nK; kt++) {
        int s = kt & 1;
        uint32_t soff = (uint32_t)s * STAGE_BYTES;

        // ---- issue ALL raw loads before waiting (latency overlaps the wait) ----
        float4 tb[8], ta[8];
#pragma unroll
        for (int j = 0; j < 8; j++)
            tb[j] = *(const float4*)(bP + (size_t)(kt * BK + j) * N);
#pragma unroll
        for (int j = 0; j < 8; j++) {
            if (av[j]) ta[j] = *(const float4*)(aP[j] + kt * BK);
            else       ta[j] = make_float4(0.f, 0.f, 0.f, 0.f);
        }

        if (kt >= 2) {
            if (s == 0) { mbar_wait(sb + 8, ph0);  ph0 ^= 1; }
            else        { mbar_wait(sb + 16, ph1); ph1 ^= 1; }
        }

        // ---- A pack + STS ----
#pragma unroll
        for (int j = 0; j < 8; j++) {
            uint32_t p0 = pack2(ta[j].x, ta[j].y), p1 = pack2(ta[j].z, ta[j].w);
            asm volatile("st.shared.v2.b32 [%0], {%1,%2};"
                :: "r"(aAddr[j] + soff), "r"(p0), "r"(p1) : "memory");
        }
        // ---- B transpose-pack + STS: per n-col c, 8 consecutive k halves = one v4 ----
        {
            const float* tf = (const float*)tb;   // tb[j] components: tf[4*j + c]
#pragma unroll
            for (int c = 0; c < 4; c++) {
                uint32_t q0 = pack2(tf[c],      tf[4 + c]);
                uint32_t q1 = pack2(tf[8 + c],  tf[12 + c]);
                uint32_t q2 = pack2(tf[16 + c], tf[20 + c]);
                uint32_t q3 = pack2(tf[24 + c], tf[28 + c]);
                asm volatile("st.shared.v4.b32 [%0], {%1,%2,%3,%4};"
                    :: "r"(bAddr[c] + soff), "r"(q0), "r"(q1), "r"(q2), "r"(q3) : "memory");
            }
        }
        asm volatile("fence.proxy.async.shared::cta;" ::: "memory");
        __syncthreads();

        if (tid == 0) {
            asm volatile("tcgen05.fence::after_thread_sync;" ::: "memory");
            uint64_t ad = make_desc_k(tiles + soff);
            uint64_t bd = make_desc_k(tiles + soff + STAGE_A);
#pragma unroll
            for (int ks = 0; ks < 4; ks++)   // K=16 per mma, +2 desc units (32B)
                mma_f16_ss(tmem, ad + ks * 2, bd + ks * 2, (uint32_t)((kt | ks) != 0));
            tc_commit(sb + 8 + 8 * s);
        }
    }

    if (((nK - 1) & 1) == 0) mbar_wait(sb + 8, ph0);
    else                     mbar_wait(sb + 16, ph1);
    asm volatile("tcgen05.fence::after_thread_sync;" ::: "memory");

    if (wid < 4) {
        int m = wid * 32 + lane;
        int grm = row0 + m;
        float* dst = (float*)0;
        if (grm < cnt) { int p = g_list[e * M_TOK + grm]; dst = C + (size_t)p * ldC + n0; }
#pragma unroll
        for (int cb = 0; cb < BN; cb += 32) {
            uint32_t r[32];
            asm volatile(
                "tcgen05.ld.sync.aligned.32x32b.x32.b32 "
                "{%0,%1,%2,%3,%4,%5,%6,%7,%8,%9,%10,%11,%12,%13,%14,%15,"
                "%16,%17,%18,%19,%20,%21,%22,%23,%24,%25,%26,%27,%28,%29,%30,%31}, [%32];"
                : "=r"(r[0]), "=r"(r[1]), "=r"(r[2]), "=r"(r[3]), "=r"(r[4]), "=r"(r[5]),
                  "=r"(r[6]), "=r"(r[7]), "=r"(r[8]), "=r"(r[9]), "=r"(r[10]), "=r"(r[11]),
                  "=r"(r[12]), "=r"(r[13]), "=r"(r[14]), "=r"(r[15]), "=r"(r[16]), "=r"(r[17]),
                  "=r"(r[18]), "=r"(r[19]), "=r"(r[20]), "=r"(r[21]), "=r"(r[22]), "=r"(r[23]),
                  "=r"(r[24]), "=r"(r[25]), "=r"(r[26]), "=r"(r[27]), "=r"(r[28]), "=r"(r[29]),
                  "=r"(r[30]), "=r"(r[31])
                : "r"(tmem + cb));
            asm volatile("tcgen05.wait::ld.sync.aligned;" ::: "memory");
            if (dst) {
#pragma unroll
                for (int j = 0; j < 8; j++) {
                    float4 v;
                    v.x = __uint_as_float(r[4 * j + 0]); v.y = __uint_as_float(r[4 * j + 1]);
                    v.z = __uint_as_float(r[4 * j + 2]); v.w = __uint_as_float(r[4 * j + 3]);
                    *(float4*)(dst + cb + 4 * j) = v;
                }
            }
        }
    }
    __syncthreads();
    if (wid == 0) {
        asm volatile("tcgen05.relinquish_alloc_permit.cta_group::1.sync.aligned;");
        asm volatile("tcgen05.dealloc.cta_group::1.sync.aligned.b32 %0, %1;" :: "r"(tmem), "r"(128u));
    }
#else
    // Never-selected safety net (a-cubin is picked at runtime): naive correct GEMM.
    for (int r = tid >> 5; row0 + r < cnt && r < BM; r += 8) {
        int p = g_list[e * M_TOK + row0 + r];
        int sr = (MODE == 1) ? (p >> 1) : p;
        const float* a = Asrc + (size_t)sr * ldA;
        for (int n = lane; n < BN; n += 32) {
            float acc = 0.f;
            for (int k = 0; k < KDIM; k++) acc += a[k] * W[(size_t)k * N + n0 + n];
            C[(size_t)p * ldC + n0 + n] = acc;
        }
    }
#endif
}

__global__ void silu_mul_kernel() {
    const int I4 = I_DIM / 4;
    long long idx = (long long)blockIdx.x * blockDim.x + threadIdx.x;
    long long p = idx / I4;
    int i4 = (int)(idx % I4);
    const float* gp = g_gu + p * (2 * I_DIM);
    float4 gv = *(const float4*)(gp + i4 * 4);
    float4 uv = *(const float4*)(gp + I_DIM + i4 * 4);
    float4 h;
    h.x = gv.x / (1.f + expf(-gv.x)) * uv.x;
    h.y = gv.y / (1.f + expf(-gv.y)) * uv.y;
    h.z = gv.z / (1.f + expf(-gv.z)) * uv.z;
    h.w = gv.w / (1.f + expf(-gv.w)) * uv.w;
    *(float4*)(g_h + p * I_DIM + i4 * 4) = h;
}

__global__ void combine_kernel(float* __restrict__ out) {
    const int H4 = H_DIM / 4;
    int idx = blockIdx.x * blockDim.x + threadIdx.x;
    int m = idx / H4;
    int h4 = idx % H4;
    float w0 = g_pw[2 * m + 0];
    float w1 = g_pw[2 * m + 1];
    float4 d0 = *(const float4*)(g_dn + (long long)(2 * m + 0) * H_DIM + h4 * 4);
    float4 d1 = *(const float4*)(g_dn + (long long)(2 * m + 1) * H_DIM + h4 * 4);
    float4 o;
    o.x = w0 * d0.x + w1 * d1.x;
    o.y = w0 * d0.y + w1 * d1.y;
    o.z = w0 * d0.z + w1 * d1.z;
    o.w = w0 * d0.w + w1 * d1.w;
    *(float4*)(out + (long long)m * H_DIM + h4 * 4) = o;
}

extern "C" void kernel_launch(void* const* d_in, const int* in_sizes, int n_in,
                              void* d_out, int out_size) {
    const float* x  = (const float*)d_in[0];
    const float* wg = (const float*)d_in[1];
    const float* w1 = (const float*)d_in[2];
    const float* w2 = (const float*)d_in[3];
    float* out = (float*)d_out;
    (void)in_sizes; (void)n_in; (void)out_size;

    cudaFuncSetAttribute(gemm_kernel<1, H_DIM>,
                         cudaFuncAttributeMaxDynamicSharedMemorySize, SMEM_DYN_BYTES);
    cudaFuncSetAttribute(gemm_kernel<2, I_DIM>,
                         cudaFuncAttributeMaxDynamicSharedMemorySize, SMEM_DYN_BYTES);

    reset_kernel<<<1, 32>>>();
    router_kernel<<<M_TOK / 8, 256>>>(x, wg);

    dim3 grid1(M_TOK / BM, (2 * I_DIM) / BN, E_NUM);
    gemm_kernel<1, H_DIM><<<grid1, 256, SMEM_DYN_BYTES>>>(x, w1, 2 * I_DIM, H_DIM, 2 * I_DIM);

    silu_mul_kernel<<<(P_NUM * (I_DIM / 4)) / 256, 256>>>();

    dim3 grid2(M_TOK / BM, H_DIM / BN, E_NUM);
    gemm_kernel<2, I_DIM><<<grid2, 256, SMEM_DYN_BYTES>>>(x, w2, H_DIM, I_DIM, H_DIM);

    combine_kernel<<<(M_TOK * (H_DIM / 4)) / 256, 256>>>(out);
}